// round 12
// baseline (speedup 1.0000x reference)
#include <cuda_runtime.h>
#include <cstdint>

#define SEQ_LEN   2048
#define STATE_LEN 1024
#define N_POI     10000
#define ROW_BYTES (N_POI * 4)            // 40000, 16B-aligned
#define EPS_VAL   1e-6f
#define THREADS   256
#define PER_T     (SEQ_LEN / THREADS)    // 8
#define GRID      (STATE_LEN / 2)        // 512 CTAs, 2 rows each: balanced

__device__ __forceinline__ void mbar_wait(uint32_t addr, uint32_t parity)
{
    uint32_t done;
    asm volatile(
        "{\n\t"
        ".reg .pred p;\n\t"
        "mbarrier.try_wait.parity.acquire.cta.shared::cta.b64 p, [%1], %2;\n\t"
        "selp.b32 %0, 1, 0, p;\n\t"
        "}"
        : "=r"(done) : "r"(addr), "r"(parity) : "memory");
    if (!done) {
        asm volatile(
            "{\n\t"
            ".reg .pred P1;\n\t"
            "W_%=:\n\t"
            "mbarrier.try_wait.parity.acquire.cta.shared::cta.b64 P1, [%0], %1, 0x989680;\n\t"
            "@P1 bra.uni D_%=;\n\t"
            "bra.uni W_%=;\n\t"
            "D_%=:\n\t"
            "}"
            :: "r"(addr), "r"(parity) : "memory");
    }
}

// Bulk copy with L2 evict_last hint: keeps matrix rows resident in L2 across
// graph replays (L2 persists across launches; only L1 is flushed).
__device__ __forceinline__ void tma_row(uint32_t mb, uint32_t dst, const char* src)
{
    asm volatile("mbarrier.arrive.expect_tx.shared.b64 _, [%0], %1;"
                 :: "r"(mb), "r"((uint32_t)ROW_BYTES) : "memory");
    asm volatile(
        "{\n\t"
        ".reg .b64 pol;\n\t"
        "createpolicy.fractional.L2::evict_last.b64 pol, 1.0;\n\t"
        "cp.async.bulk.shared::cluster.global.mbarrier::complete_tx::bytes.L2::cache_hint "
        "[%0], [%1], %2, [%3], pol;\n\t"
        "}"
        :: "r"(dst), "l"(src), "r"((uint32_t)ROW_BYTES), "r"(mb) : "memory");
}

__global__ __launch_bounds__(THREADS)
void attn_loc_kernel(const int* __restrict__ his,
                     const int* __restrict__ cur,
                     const float* __restrict__ mat,
                     float* __restrict__ out)
{
    __shared__ alignas(128) float srow[N_POI];   // 40000 B single buffer
    __shared__ float sred[THREADS / 32];
    __shared__ alignas(8) uint64_t mbar;

    const int tid  = threadIdx.x;
    const int row0 = blockIdx.x;
    const int row1 = blockIdx.x + GRID;
    const uint32_t mb  = (uint32_t)__cvta_generic_to_shared(&mbar);
    const uint32_t dst = (uint32_t)__cvta_generic_to_shared(srow);

    const char* src1 = nullptr;
    if (tid == 0) {
        asm volatile("mbarrier.init.shared.b64 [%0], %1;"
                     :: "r"(mb), "r"(1) : "memory");
        const char* src0 = (const char*)mat + (size_t)__ldg(cur + row0) * ROW_BYTES;
        src1             = (const char*)mat + (size_t)__ldg(cur + row1) * ROW_BYTES;
        tma_row(mb, dst, src0);          // row0 in flight immediately
    }

    // Index prefetch overlaps the TMA flight (his is tiny, L2-resident).
    int cidx[PER_T];
#pragma unroll
    for (int k = 0; k < PER_T; k++)
        cidx[k] = __ldg(his + tid + k * THREADS);

    __syncthreads();                     // publish mbarrier init

#pragma unroll
    for (int half = 0; half < 2; half++) {
        mbar_wait(mb, (uint32_t)half);   // row landed (parity 0 then 1)

        // Gather from smem into registers, local max
        float v[PER_T];
        float mx = -INFINITY;
#pragma unroll
        for (int k = 0; k < PER_T; k++) {
            const float d = srow[cidx[k]];
            const float e = (d != 0.0f) ? __fdividef(1.0f, d) : EPS_VAL;
            v[k] = e;
            mx = fmaxf(mx, e);
        }

        // Block max reduction
#pragma unroll
        for (int o = 16; o; o >>= 1)
            mx = fmaxf(mx, __shfl_xor_sync(0xffffffffu, mx, o));
        if ((tid & 31) == 0) sred[tid >> 5] = mx;
        __syncthreads();                 // all srow reads complete here

        // Copy row1 into the SAME buffer: its flight overlaps row0's
        // entire epilogue (reductions + exp + store).
        if (half == 0 && tid == 0)
            tma_row(mb, dst, src1);

        float bmax = sred[0];
#pragma unroll
        for (int w = 1; w < THREADS / 32; w++) bmax = fmaxf(bmax, sred[w]);
        __syncthreads();

        // exp + local sum
        float sum = 0.0f;
#pragma unroll
        for (int k = 0; k < PER_T; k++) {
            const float e = __expf(v[k] - bmax);
            v[k] = e;
            sum += e;
        }

        // Block sum reduction
#pragma unroll
        for (int o = 16; o; o >>= 1)
            sum += __shfl_xor_sync(0xffffffffu, sum, o);
        if ((tid & 31) == 0) sred[tid >> 5] = sum;
        __syncthreads();
        float bsum = 0.0f;
#pragma unroll
        for (int w = 0; w < THREADS / 32; w++) bsum += sred[w];
        __syncthreads();                 // sred safe to reuse next half

        // Normalize + streaming store (evict_first: don't let the 8MB/replay
        // of output evict the L2-resident matrix rows).
        const float inv = __fdividef(1.0f, bsum);
        const int row = half ? row1 : row0;
        float* __restrict__ orow = out + (size_t)row * SEQ_LEN;
#pragma unroll
        for (int k = 0; k < PER_T; k++)
            __stcs(orow + tid + k * THREADS, v[k] * inv);
    }
}

extern "C" void kernel_launch(void* const* d_in, const int* in_sizes, int n_in,
                              void* d_out, int out_size)
{
    const int*   his = (const int*)d_in[0];
    const int*   cur = (const int*)d_in[1];
    const float* mat = (const float*)d_in[2];
    float*       out = (float*)d_out;

    attn_loc_kernel<<<GRID, THREADS>>>(his, cur, mat, out);
}

// round 13
// speedup vs baseline: 1.3506x; 1.3506x over previous
#include <cuda_runtime.h>
#include <cstdint>

#define SEQ_LEN   2048
#define STATE_LEN 1024
#define N_POI     10000
#define ROW_BYTES (N_POI * 4)            // 40000, 16B-aligned
#define EPS_VAL   1e-6f
#define THREADS   256
#define PER_T     (SEQ_LEN / THREADS)    // 8
#define GRID      (STATE_LEN / 2)        // 512 CTAs -> single wave, 2 rows each

__device__ __forceinline__ void mbar_wait(uint32_t addr, uint32_t parity)
{
    uint32_t done;
    asm volatile(
        "{\n\t"
        ".reg .pred p;\n\t"
        "mbarrier.try_wait.parity.acquire.cta.shared::cta.b64 p, [%1], %2;\n\t"
        "selp.b32 %0, 1, 0, p;\n\t"
        "}"
        : "=r"(done) : "r"(addr), "r"(parity) : "memory");
    if (!done) {
        asm volatile(
            "{\n\t"
            ".reg .pred P1;\n\t"
            "W_%=:\n\t"
            "mbarrier.try_wait.parity.acquire.cta.shared::cta.b64 P1, [%0], %1, 0x989680;\n\t"
            "@P1 bra.uni D_%=;\n\t"
            "bra.uni W_%=;\n\t"
            "D_%=:\n\t"
            "}"
            :: "r"(addr), "r"(parity) : "memory");
    }
}

__device__ __forceinline__ void tma_row(uint32_t mb, uint32_t dst, const char* src)
{
    asm volatile("mbarrier.arrive.expect_tx.shared.b64 _, [%0], %1;"
                 :: "r"(mb), "r"((uint32_t)ROW_BYTES) : "memory");
    asm volatile(
        "cp.async.bulk.shared::cluster.global.mbarrier::complete_tx::bytes "
        "[%0], [%1], %2, [%3];"
        :: "r"(dst), "l"(src), "r"((uint32_t)ROW_BYTES), "r"(mb) : "memory");
}

__global__ __launch_bounds__(THREADS)
void attn_loc_kernel(const int* __restrict__ his,
                     const int* __restrict__ cur,
                     const float* __restrict__ mat,
                     float* __restrict__ out)
{
    __shared__ alignas(128) float srow[N_POI];   // 40000 B single buffer
    __shared__ float sred[THREADS / 32];
    __shared__ alignas(8) uint64_t mbar;

    const int tid  = threadIdx.x;
    const int row0 = blockIdx.x;
    const int row1 = blockIdx.x + GRID;
    const uint32_t mb  = (uint32_t)__cvta_generic_to_shared(&mbar);
    const uint32_t dst = (uint32_t)__cvta_generic_to_shared(srow);

    const char* src1 = nullptr;
    if (tid == 0) {
        asm volatile("mbarrier.init.shared.b64 [%0], %1;"
                     :: "r"(mb), "r"(1) : "memory");
        const char* src0 = (const char*)mat + (size_t)__ldg(cur + row0) * ROW_BYTES;
        src1             = (const char*)mat + (size_t)__ldg(cur + row1) * ROW_BYTES;
        tma_row(mb, dst, src0);          // row0 in flight immediately
    }

    // Index prefetch overlaps the TMA flight (his is tiny, L2-resident).
    int cidx[PER_T];
#pragma unroll
    for (int k = 0; k < PER_T; k++)
        cidx[k] = __ldg(his + tid + k * THREADS);

    __syncthreads();                     // publish mbarrier init

#pragma unroll
    for (int half = 0; half < 2; half++) {
        mbar_wait(mb, (uint32_t)half);   // row landed (parity 0 then 1)

        // Gather from smem into registers, local max
        float v[PER_T];
        float mx = -INFINITY;
#pragma unroll
        for (int k = 0; k < PER_T; k++) {
            const float d = srow[cidx[k]];
            const float e = (d != 0.0f) ? __fdividef(1.0f, d) : EPS_VAL;
            v[k] = e;
            mx = fmaxf(mx, e);
        }

        // Block max reduction
#pragma unroll
        for (int o = 16; o; o >>= 1)
            mx = fmaxf(mx, __shfl_xor_sync(0xffffffffu, mx, o));
        if ((tid & 31) == 0) sred[tid >> 5] = mx;
        __syncthreads();                 // all srow reads complete here

        // Prefetch row1 into the SAME buffer: its flight overlaps row0's
        // entire epilogue (reductions + exp + store).
        if (half == 0 && tid == 0)
            tma_row(mb, dst, src1);

        float bmax = sred[0];
#pragma unroll
        for (int w = 1; w < THREADS / 32; w++) bmax = fmaxf(bmax, sred[w]);
        __syncthreads();

        // exp + local sum
        float sum = 0.0f;
#pragma unroll
        for (int k = 0; k < PER_T; k++) {
            const float e = __expf(v[k] - bmax);
            v[k] = e;
            sum += e;
        }

        // Block sum reduction
#pragma unroll
        for (int o = 16; o; o >>= 1)
            sum += __shfl_xor_sync(0xffffffffu, sum, o);
        if ((tid & 31) == 0) sred[tid >> 5] = sum;
        __syncthreads();
        float bsum = 0.0f;
#pragma unroll
        for (int w = 0; w < THREADS / 32; w++) bsum += sred[w];
        __syncthreads();                 // sred safe to reuse next half

        // Normalize + coalesced store
        const float inv = __fdividef(1.0f, bsum);
        const int row = half ? row1 : row0;
        float* __restrict__ orow = out + (size_t)row * SEQ_LEN;
#pragma unroll
        for (int k = 0; k < PER_T; k++)
            orow[tid + k * THREADS] = v[k] * inv;
    }
}

extern "C" void kernel_launch(void* const* d_in, const int* in_sizes, int n_in,
                              void* d_out, int out_size)
{
    const int*   his = (const int*)d_in[0];
    const int*   cur = (const int*)d_in[1];
    const float* mat = (const float*)d_in[2];
    float*       out = (float*)d_out;

    attn_loc_kernel<<<GRID, THREADS>>>(his, cur, mat, out);
}